// round 11
// baseline (speedup 1.0000x reference)
#include <cuda_runtime.h>
#include <cuda_fp16.h>
#include <math.h>

#define PP   4096   // D*H*W
#define CC   192
#define HIDN 384
#define MLPH 768
#define NQKV 576

static constexpr size_t O_SUM   = 0;
static constexpr size_t O_SUMSQ = 256;
static constexpr size_t O_FAC   = 512;
static constexpr size_t O_QKV   = 1024;
static constexpr size_t O_ATTN  = O_QKV  + (size_t)PP*NQKV;
static constexpr size_t O_X2T   = O_ATTN + (size_t)PP*CC;
static constexpr size_t O_X2C   = O_X2T  + (size_t)PP*CC;
static constexpr size_t O_M1    = O_X2C  + (size_t)PP*CC;
static constexpr size_t SCRATCH_TOTAL = O_M1 + (size_t)PP*MLPH;

__device__ float g_scratch[SCRATCH_TOTAL];

// ---------------------------------------------------------------------------
// Per-channel sum & sum-of-squares over 4096 contiguous spatial elements
// ---------------------------------------------------------------------------
__global__ __launch_bounds__(256) void reduce_kernel(
    const float* __restrict__ xc, float* __restrict__ sum, float* __restrict__ sumsq)
{
    int c = blockIdx.x;
    const float4* xr = (const float4*)(xc + (size_t)c * PP);
    float s = 0.f, ss = 0.f;
    for (int i = threadIdx.x; i < PP/4; i += 256) {
        float4 v = xr[i];
        s  += v.x + v.y + v.z + v.w;
        ss += v.x*v.x + v.y*v.y + v.z*v.z + v.w*v.w;
    }
    for (int o = 16; o; o >>= 1) {
        s  += __shfl_xor_sync(0xffffffffu, s,  o);
        ss += __shfl_xor_sync(0xffffffffu, ss, o);
    }
    __shared__ float sh_s[8], sh_ss[8];
    int w = threadIdx.x >> 5, l = threadIdx.x & 31;
    if (l == 0) { sh_s[w] = s; sh_ss[w] = ss; }
    __syncthreads();
    if (threadIdx.x == 0) {
        float a = 0.f, b = 0.f;
        #pragma unroll
        for (int i = 0; i < 8; i++) { a += sh_s[i]; b += sh_ss[i]; }
        sum[c] = a; sumsq[c] = b;
    }
}

// ---------------------------------------------------------------------------
// Gamma MLP (coalesced, warp-per-row)
// ---------------------------------------------------------------------------
__global__ __launch_bounds__(1024) void gamma_kernel(
    const float* __restrict__ sum, const float* __restrict__ sumsq,
    const float* __restrict__ scale,
    const float* __restrict__ w1, const float* __restrict__ b1,
    const float* __restrict__ w2, const float* __restrict__ b2,
    float* __restrict__ fac)
{
    __shared__ float stats[CC];
    __shared__ float hbuf[HIDN];
    int tid = threadIdx.x, warp = tid >> 5, lane = tid & 31;
    if (tid < CC) stats[tid] = sum[tid] * (1.0f / PP);
    __syncthreads();
    for (int r = warp; r < HIDN; r += 32) {
        float a = 0.f;
        const float* wr = w1 + (size_t)r * CC;
        #pragma unroll
        for (int c = lane; c < CC; c += 32) a += stats[c] * wr[c];
        for (int o = 16; o; o >>= 1) a += __shfl_xor_sync(0xffffffffu, a, o);
        if (lane == 0) hbuf[r] = fmaxf(a + b1[r], 0.f);
    }
    __syncthreads();
    for (int r = warp; r < CC; r += 32) {
        float a = 0.f;
        const float* wr = w2 + (size_t)r * HIDN;
        #pragma unroll
        for (int c = lane; c < HIDN; c += 32) a += hbuf[c] * wr[c];
        for (int o = 16; o; o >>= 1) a += __shfl_xor_sync(0xffffffffu, a, o);
        if (lane == 0) {
            float gamma = 1.f / (1.f + expf(-(a + b2[r])));
            fac[r] = scale[r] * gamma * rsqrtf(sumsq[r] * (1.0f / PP) + 1e-6f);
        }
    }
}

// ---------------------------------------------------------------------------
// tf32 tensor-core GEMM (unchanged from R2)
// ---------------------------------------------------------------------------
__device__ __forceinline__ float gelu_f(float v) {
    return 0.5f * v * (1.f + erff(v * 0.70710678118654752f));
}
__device__ __forceinline__ unsigned f2tf(float f) {
    unsigned u; asm("cvt.rna.tf32.f32 %0, %1;" : "=r"(u) : "f"(f)); return u;
}
__device__ __forceinline__ void mma_tf32(float* c, const unsigned* a, const unsigned* b) {
    asm volatile(
        "mma.sync.aligned.m16n8k8.row.col.f32.tf32.tf32.f32 "
        "{%0,%1,%2,%3}, {%4,%5,%6,%7}, {%8,%9}, {%0,%1,%2,%3};"
        : "+f"(c[0]), "+f"(c[1]), "+f"(c[2]), "+f"(c[3])
        : "r"(a[0]), "r"(a[1]), "r"(a[2]), "r"(a[3]), "r"(b[0]), "r"(b[1]));
}

#define ASTR 136
#define BSTR 72

template<int MODE, int ASRC>
__global__ __launch_bounds__(256) void gemm_kernel(
    const float* __restrict__ A, const float* __restrict__ fac,
    const float* __restrict__ W, const float* __restrict__ bias,
    float* __restrict__ out, int N, int K,
    const float* __restrict__ res, float* __restrict__ out2)
{
    __shared__ float As[2][16 * ASTR];
    __shared__ float Ws[2][16 * BSTR];

    int bm = blockIdx.y * 128, bn = blockIdx.x * 64;
    int tid = threadIdx.x;
    int warp = tid >> 5, lane = tid & 31;
    int warp_m = warp & 3, warp_n = warp >> 2;
    int lq = lane & 3, l4 = lane >> 2;

    float acc[2][4][4];
    #pragma unroll
    for (int i = 0; i < 2; i++)
        #pragma unroll
        for (int j = 0; j < 4; j++)
            #pragma unroll
            for (int e = 0; e < 4; e++) acc[i][j][e] = 0.f;

    float4 ra[2], rb;
    int nPanels = K / 16;

    auto ldg_panel = [&](int p) {
        int k0 = p * 16;
        if (ASRC == 0) {
            #pragma unroll
            for (int u = 0; u < 2; u++) {
                int t = tid + u * 256;
                int m = t & 127, kc = t >> 7;
                ra[u] = *(const float4*)(A + (size_t)(bm + m) * K + k0 + kc * 4);
            }
        } else {
            #pragma unroll
            for (int u = 0; u < 2; u++) {
                int t = tid + u * 256;
                int mq = t & 31, k = t >> 5;
                float4 v = *(const float4*)(A + (size_t)(k0 + k) * PP + bm + mq * 4);
                float f = fac[k0 + k];
                v.x *= f; v.y *= f; v.z *= f; v.w *= f;
                ra[u] = v;
            }
        }
        int n = tid & 63, kc = tid >> 6;
        rb = *(const float4*)(W + (size_t)(bn + n) * K + k0 + kc * 4);
    };

    auto sts_panel = [&](int buf) {
        if (ASRC == 0) {
            #pragma unroll
            for (int u = 0; u < 2; u++) {
                int t = tid + u * 256;
                int m = t & 127, kc = t >> 7;
                float* dst = &As[buf][(kc * 4) * ASTR + m];
                dst[0 * ASTR] = __uint_as_float(f2tf(ra[u].x));
                dst[1 * ASTR] = __uint_as_float(f2tf(ra[u].y));
                dst[2 * ASTR] = __uint_as_float(f2tf(ra[u].z));
                dst[3 * ASTR] = __uint_as_float(f2tf(ra[u].w));
            }
        } else {
            #pragma unroll
            for (int u = 0; u < 2; u++) {
                int t = tid + u * 256;
                int mq = t & 31, k = t >> 5;
                float* dst = &As[buf][k * ASTR + mq * 4];
                dst[0] = __uint_as_float(f2tf(ra[u].x));
                dst[1] = __uint_as_float(f2tf(ra[u].y));
                dst[2] = __uint_as_float(f2tf(ra[u].z));
                dst[3] = __uint_as_float(f2tf(ra[u].w));
            }
        }
        int n = tid & 63, kc = tid >> 6;
        float* dst = &Ws[buf][(kc * 4) * BSTR + n];
        dst[0 * BSTR] = __uint_as_float(f2tf(rb.x));
        dst[1 * BSTR] = __uint_as_float(f2tf(rb.y));
        dst[2 * BSTR] = __uint_as_float(f2tf(rb.z));
        dst[3 * BSTR] = __uint_as_float(f2tf(rb.w));
    };

    auto compute = [&](int buf) {
        const float* as = As[buf];
        const float* ws = Ws[buf];
        #pragma unroll
        for (int ks = 0; ks < 2; ks++) {
            int kb = ks * 8;
            unsigned af[2][4];
            #pragma unroll
            for (int mt = 0; mt < 2; mt++) {
                int m0 = warp_m * 32 + mt * 16 + l4;
                const float* p = as + (kb + lq) * ASTR + m0;
                af[mt][0] = __float_as_uint(p[0]);
                af[mt][1] = __float_as_uint(p[8]);
                af[mt][2] = __float_as_uint(p[4 * ASTR]);
                af[mt][3] = __float_as_uint(p[4 * ASTR + 8]);
            }
            unsigned bf[4][2];
            #pragma unroll
            for (int nt = 0; nt < 4; nt++) {
                int n0 = warp_n * 32 + nt * 8 + l4;
                const float* p = ws + (kb + lq) * BSTR + n0;
                bf[nt][0] = __float_as_uint(p[0]);
                bf[nt][1] = __float_as_uint(p[4 * BSTR]);
            }
            #pragma unroll
            for (int mt = 0; mt < 2; mt++)
                #pragma unroll
                for (int nt = 0; nt < 4; nt++)
                    mma_tf32(acc[mt][nt], af[mt], bf[nt]);
        }
    };

    ldg_panel(0);
    sts_panel(0);
    __syncthreads();
    for (int p = 0; p < nPanels; p++) {
        if (p + 1 < nPanels) ldg_panel(p + 1);
        compute(p & 1);
        if (p + 1 < nPanels) { sts_panel((p + 1) & 1); __syncthreads(); }
    }

    #pragma unroll
    for (int mt = 0; mt < 2; mt++) {
        int r0 = bm + warp_m * 32 + mt * 16 + l4;
        #pragma unroll
        for (int nt = 0; nt < 4; nt++) {
            int c0 = bn + warp_n * 32 + nt * 8 + lq * 2;
            #pragma unroll
            for (int e = 0; e < 4; e++) {
                int m = r0 + (e >> 1) * 8;
                int n = c0 + (e & 1);
                float v = acc[mt][nt][e] + bias[n];
                if constexpr (MODE == 0) {
                    out[(size_t)m * N + n] = v;
                } else if constexpr (MODE == 1) {
                    v += res[(size_t)n * PP + m];
                    out[(size_t)m * N + n] = v;
                    out2[(size_t)n * PP + m] = v;
                } else if constexpr (MODE == 2) {
                    out[(size_t)m * N + n] = gelu_f(v);
                } else {
                    v += res[(size_t)m * N + n];
                    out[(size_t)n * PP + m] = v;
                }
            }
        }
    }
}

// ---------------------------------------------------------------------------
// Tensor-core 3D neighborhood attention.
// Block = (4x4x4 query tile, head), 256 threads (8 warps = 4 m x 2 n-halves).
// S = Q[64x32] @ K_halo[512x32]^T via fp16 mma.m16n8k16, per-query window
// mask -> exp (no max subtraction: |scores| << 80), rowsum, then
// O = P @ V_halo with P passed register-to-register (accum layout == A-frag
// layout). fp16 operands, fp32 accumulation throughout.
// ---------------------------------------------------------------------------
// smem layout (bytes):
//   K_s : [512][40] half   ->  40960   (pad 40: conflict-free B-frag loads)
//   V_t : [32][520] half   ->  33280   (transposed; 520%64==8 -> conflict-free)
//   Q_s : [64][40]  half   ->   5120
//   O0  : [64][33]  float  ->   8448   (warp_n=0 partial)
//   O1  : [64][33]  float  ->   8448   (warp_n=1 partial)
//   rsum: [2][64]   float  ->    512
#define ATTN_SMEM_BYTES (40960 + 33280 + 5120 + 8448 + 8448 + 512)

__device__ __forceinline__ void mma_fp16(float* c, const unsigned* a, unsigned b0, unsigned b1) {
    asm volatile(
        "mma.sync.aligned.m16n8k16.row.col.f32.f16.f16.f32 "
        "{%0,%1,%2,%3}, {%4,%5,%6,%7}, {%8,%9}, {%0,%1,%2,%3};"
        : "+f"(c[0]), "+f"(c[1]), "+f"(c[2]), "+f"(c[3])
        : "r"(a[0]), "r"(a[1]), "r"(a[2]), "r"(a[3]), "r"(b0), "r"(b1));
}
__device__ __forceinline__ unsigned pack_h2(float a, float b) {
    __half2 h = __floats2half2_rn(a, b);
    return *(unsigned*)&h;
}

__global__ __launch_bounds__(256, 2) void attn_mma_kernel(
    const float* __restrict__ qkv, float* __restrict__ attn_out)
{
    extern __shared__ char smem_raw[];
    __half* K_s = (__half*)smem_raw;
    __half* V_t = (__half*)(smem_raw + 40960);
    __half* Q_s = (__half*)(smem_raw + 74240);
    float*  O0  = (float*)(smem_raw + 79360);
    float*  O1  = (float*)(smem_raw + 87808);
    float*  rsum = (float*)(smem_raw + 96256);

    int tile = blockIdx.x, head = blockIdx.y;
    int td0 = (tile >> 4) * 4, th0 = ((tile >> 2) & 3) * 4, tw0 = (tile & 3) * 4;
    int hb_d = min(max(td0 - 2, 0), 8);
    int hb_h = min(max(th0 - 2, 0), 8);
    int hb_w = min(max(tw0 - 2, 0), 8);

    int tid = threadIdx.x;

    // ---- stage K (row-major) and V (transposed) halos, fp32 -> fp16 ----
    #pragma unroll 4
    for (int it = 0; it < 32; ++it) {
        int idx = tid + it * 256;            // 0..8191: (pos n, float2-chunk jp)
        int n = idx >> 4, jp = idx & 15;
        int d = hb_d + (n >> 6), h = hb_h + ((n >> 3) & 7), w = hb_w + (n & 7);
        size_t gb = (size_t)((d * 16 + h) * 16 + w) * NQKV + head * 32 + jp * 2;
        float2 kv = *(const float2*)(qkv + gb + 192);
        *(__half2*)(K_s + n * 40 + jp * 2) = __floats2half2_rn(kv.x, kv.y);
        float2 vv = *(const float2*)(qkv + gb + 384);
        V_t[(jp * 2)     * 520 + n] = __float2half_rn(vv.x);
        V_t[(jp * 2 + 1) * 520 + n] = __float2half_rn(vv.y);
    }
    const float scale_qk = 0.17677669529663687f;  // 32^-0.5, folded into Q
    #pragma unroll
    for (int it = 0; it < 4; ++it) {
        int idx = tid + it * 256;            // 0..1023
        int m = idx >> 4, jp = idx & 15;
        int gd = td0 + (m >> 4), gh = th0 + ((m >> 2) & 3), gw = tw0 + (m & 3);
        size_t gb = (size_t)((gd * 16 + gh) * 16 + gw) * NQKV + head * 32 + jp * 2;
        float2 qv = *(const float2*)(qkv + gb);
        *(__half2*)(Q_s + m * 40 + jp * 2) =
            __floats2half2_rn(qv.x * scale_qk, qv.y * scale_qk);
    }
    __syncthreads();

    int warp = tid >> 5, lane = tid & 31;
    int warp_m = warp & 3, warp_n = warp >> 2;
    int g = lane >> 2, q = lane & 3;
    int r0 = warp_m * 16 + g;
    int r1 = r0 + 8;

    // per-row window lows in halo coords (each in [0,3]; window width 5)
    int ld0, lh0, lw0, ld1, lh1, lw1;
    {
        int qd = r0 >> 4, qh = (r0 >> 2) & 3, qw = r0 & 3;
        ld0 = min(max(td0 + qd - 2, 0), 11) - hb_d;
        lh0 = min(max(th0 + qh - 2, 0), 11) - hb_h;
        lw0 = min(max(tw0 + qw - 2, 0), 11) - hb_w;
        qd = r1 >> 4; qh = (r1 >> 2) & 3; qw = r1 & 3;
        ld1 = min(max(td0 + qd - 2, 0), 11) - hb_d;
        lh1 = min(max(th0 + qh - 2, 0), 11) - hb_h;
        lw1 = min(max(tw0 + qw - 2, 0), 11) - hb_w;
    }
    // per-thread w-column validity (cols 2q, 2q+1) -- fixed across all tiles
    bool wv00 = (2*q   >= lw0) && (2*q   < lw0 + 5);
    bool wv01 = (2*q+1 >= lw0) && (2*q+1 < lw0 + 5);
    bool wv10 = (2*q   >= lw1) && (2*q   < lw1 + 5);
    bool wv11 = (2*q+1 >= lw1) && (2*q+1 < lw1 + 5);

    // Q A-fragments (2 k-chunks of 16)
    unsigned qa[2][4];
    #pragma unroll
    for (int kc = 0; kc < 2; ++kc) {
        const __half* qp = Q_s + kc * 16 + 2 * q;
        qa[kc][0] = *(const unsigned*)(qp + r0 * 40);
        qa[kc][1] = *(const unsigned*)(qp + r1 * 40);
        qa[kc][2] = *(const unsigned*)(qp + r0 * 40 + 8);
        qa[kc][3] = *(const unsigned*)(qp + r1 * 40 + 8);
    }

    float oacc[4][4];
    #pragma unroll
    for (int i = 0; i < 4; i++)
        #pragma unroll
        for (int e = 0; e < 4; e++) oacc[i][e] = 0.f;
    float rs0 = 0.f, rs1 = 0.f;

    #pragma unroll
    for (int chunk = 0; chunk < 4; ++chunk) {
        int J0 = warp_n * 32 + chunk * 8;    // first n-tile (8 halo cols each)

        // ---- S = Q K^T over 8 n-tiles ----
        float c[8][4];
        #pragma unroll
        for (int j = 0; j < 8; j++)
            #pragma unroll
            for (int e = 0; e < 4; e++) c[j][e] = 0.f;
        #pragma unroll
        for (int j = 0; j < 8; ++j) {
            const __half* kp = K_s + (size_t)(8 * (J0 + j) + g) * 40 + 2 * q;
            #pragma unroll
            for (int kc = 0; kc < 2; ++kc) {
                unsigned b0 = *(const unsigned*)(kp + kc * 16);
                unsigned b1 = *(const unsigned*)(kp + kc * 16 + 8);
                mma_fp16(c[j], qa[kc], b0, b1);
            }
        }

        // ---- mask + exp + pack P (fp16) ----
        unsigned plo[8], phi[8];
        #pragma unroll
        for (int j = 0; j < 8; ++j) {
            int J = J0 + j;
            int d = J >> 3, h = J & 7;       // all 8 cols of tile share (d,h)
            bool dh0 = (d >= ld0) && (d < ld0 + 5) && (h >= lh0) && (h < lh0 + 5);
            bool dh1 = (d >= ld1) && (d < ld1 + 5) && (h >= lh1) && (h < lh1 + 5);
            float e0 = (dh0 && wv00) ? __expf(c[j][0]) : 0.f;
            float e1 = (dh0 && wv01) ? __expf(c[j][1]) : 0.f;
            float e2 = (dh1 && wv10) ? __expf(c[j][2]) : 0.f;
            float e3 = (dh1 && wv11) ? __expf(c[j][3]) : 0.f;
            rs0 += e0 + e1;
            rs1 += e2 + e3;
            plo[j] = pack_h2(e0, e1);
            phi[j] = pack_h2(e2, e3);
        }

        // ---- O += P @ V over this 64-col chunk (4 k16 sub-chunks) ----
        #pragma unroll
        for (int kk = 0; kk < 4; ++kk) {
            unsigned pa[4] = { plo[2*kk], phi[2*kk], plo[2*kk+1], phi[2*kk+1] };
            int kb = J0 * 8 + kk * 16 + 2 * q;
            #pragma unroll
            for (int ot = 0; ot < 4; ++ot) {
                const __half* vp = V_t + (size_t)(ot * 8 + g) * 520 + kb;
                unsigned b0 = *(const unsigned*)vp;
                unsigned b1 = *(const unsigned*)(vp + 8);
                mma_fp16(oacc[ot], pa, b0, b1);
            }
        }
    }

    // ---- rowsum quad-reduce ----
    rs0 += __shfl_xor_sync(0xffffffffu, rs0, 1);
    rs0 += __shfl_xor_sync(0xffffffffu, rs0, 2);
    rs1 += __shfl_xor_sync(0xffffffffu, rs1, 1);
    rs1 += __shfl_xor_sync(0xffffffffu, rs1, 2);
    if (q == 0) {
        rsum[warp_n * 64 + r0] = rs0;
        rsum[warp_n * 64 + r1] = rs1;
    }

    // ---- O partials to smem ----
    float* Obuf = warp_n ? O1 : O0;
    #pragma unroll
    for (int ot = 0; ot < 4; ++ot) {
        Obuf[r0 * 33 + ot * 8 + 2 * q]     = oacc[ot][0];
        Obuf[r0 * 33 + ot * 8 + 2 * q + 1] = oacc[ot][1];
        Obuf[r1 * 33 + ot * 8 + 2 * q]     = oacc[ot][2];
        Obuf[r1 * 33 + ot * 8 + 2 * q + 1] = oacc[ot][3];
    }
    __syncthreads();

    // ---- combine halves, normalize, coalesced write ----
    #pragma unroll
    for (int i = tid; i < 64 * 32; i += 256) {
        int row = i >> 5, ch = i & 31;
        float inv = 1.f / (rsum[row] + rsum[64 + row]);
        float v = (O0[row * 33 + ch] + O1[row * 33 + ch]) * inv;
        int gd = td0 + (row >> 4), gh = th0 + ((row >> 2) & 3), gw = tw0 + (row & 3);
        attn_out[(size_t)((gd * 16 + gh) * 16 + gw) * CC + head * 32 + ch] = v;
    }
}

// ---------------------------------------------------------------------------
extern "C" void kernel_launch(void* const* d_in, const int* in_sizes, int n_in,
                              void* d_out, int out_size)
{
    const float* x      = (const float*)d_in[0];
    const float* scale1 = (const float*)d_in[1];
    const float* n1_w1  = (const float*)d_in[2];
    const float* n1_b1  = (const float*)d_in[3];
    const float* n1_w2  = (const float*)d_in[4];
    const float* n1_b2  = (const float*)d_in[5];
    const float* qkv_w  = (const float*)d_in[6];
    const float* qkv_b  = (const float*)d_in[7];
    const float* proj_w = (const float*)d_in[8];
    const float* proj_b = (const float*)d_in[9];
    const float* scale2 = (const float*)d_in[10];
    const float* n2_w1  = (const float*)d_in[11];
    const float* n2_b1  = (const float*)d_in[12];
    const float* n2_w2  = (const float*)d_in[13];
    const float* n2_b2  = (const float*)d_in[14];
    const float* mlp_w1 = (const float*)d_in[15];
    const float* mlp_b1 = (const float*)d_in[16];
    const float* mlp_w2 = (const float*)d_in[17];
    const float* mlp_b2 = (const float*)d_in[18];
    float* out = (float*)d_out;

    float* S = nullptr;
    cudaGetSymbolAddress((void**)&S, g_scratch);
    float* g_sum   = S + O_SUM;
    float* g_sumsq = S + O_SUMSQ;
    float* g_fac   = S + O_FAC;
    float* g_qkv   = S + O_QKV;
    float* g_attn  = S + O_ATTN;
    float* g_x2t   = S + O_X2T;
    float* g_x2c   = S + O_X2C;
    float* g_m1    = S + O_M1;

    cudaFuncSetAttribute(attn_mma_kernel, cudaFuncAttributeMaxDynamicSharedMemorySize, ATTN_SMEM_BYTES);

    // --- block 1: ada_rmsnorm(x) factors ---
    reduce_kernel<<<CC, 256>>>(x, g_sum, g_sumsq);
    gamma_kernel<<<1, 1024>>>(g_sum, g_sumsq, scale1, n1_w1, n1_b1, n1_w2, n1_b2, g_fac);

    // --- QKV projection (norm fused into A-stage) ---
    gemm_kernel<0, 1><<<dim3(NQKV/64, PP/128), 256>>>(x, g_fac, qkv_w, qkv_b, g_qkv, NQKV, CC, nullptr, nullptr);

    // --- neighborhood attention (tensor cores) ---
    attn_mma_kernel<<<dim3(64, 6), 256, ATTN_SMEM_BYTES>>>(g_qkv, g_attn);

    // --- output projection + residual (both layouts) ---
    gemm_kernel<1, 0><<<dim3(CC/64, PP/128), 256>>>(g_attn, nullptr, proj_w, proj_b, g_x2t, CC, CC, x, g_x2c);

    // --- block 2: ada_rmsnorm(x2) factors ---
    reduce_kernel<<<CC, 256>>>(g_x2c, g_sum, g_sumsq);
    gamma_kernel<<<1, 1024>>>(g_sum, g_sumsq, scale2, n2_w1, n2_b1, n2_w2, n2_b2, g_fac);

    // --- MLP (norm fused into A-stage of first GEMM) ---
    gemm_kernel<2, 1><<<dim3(MLPH/64, PP/128), 256>>>(g_x2c, g_fac, mlp_w1, mlp_b1, g_m1, MLPH, CC, nullptr, nullptr);
    gemm_kernel<3, 0><<<dim3(CC/64, PP/128), 256>>>(g_m1, nullptr, mlp_w2, mlp_b2, out, CC, MLPH, g_x2t, nullptr);
}

// round 12
// speedup vs baseline: 1.0012x; 1.0012x over previous
#include <cuda_runtime.h>
#include <cuda_fp16.h>
#include <math.h>

#define PP   4096   // D*H*W
#define CC   192
#define HIDN 384
#define MLPH 768
#define NQKV 576

static constexpr size_t O_SUM   = 0;
static constexpr size_t O_SUMSQ = 256;
static constexpr size_t O_FAC   = 512;
static constexpr size_t O_QKV   = 1024;
static constexpr size_t O_ATTN  = O_QKV  + (size_t)PP*NQKV;
static constexpr size_t O_X2T   = O_ATTN + (size_t)PP*CC;
static constexpr size_t O_X2C   = O_X2T  + (size_t)PP*CC;
static constexpr size_t O_M1    = O_X2C  + (size_t)PP*CC;
static constexpr size_t SCRATCH_TOTAL = O_M1 + (size_t)PP*MLPH;

__device__ float g_scratch[SCRATCH_TOTAL];

// ---------------------------------------------------------------------------
// Per-channel sum & sum-of-squares over 4096 contiguous spatial elements
// ---------------------------------------------------------------------------
__global__ __launch_bounds__(256) void reduce_kernel(
    const float* __restrict__ xc, float* __restrict__ sum, float* __restrict__ sumsq)
{
    int c = blockIdx.x;
    const float4* xr = (const float4*)(xc + (size_t)c * PP);
    float s = 0.f, ss = 0.f;
    for (int i = threadIdx.x; i < PP/4; i += 256) {
        float4 v = xr[i];
        s  += v.x + v.y + v.z + v.w;
        ss += v.x*v.x + v.y*v.y + v.z*v.z + v.w*v.w;
    }
    for (int o = 16; o; o >>= 1) {
        s  += __shfl_xor_sync(0xffffffffu, s,  o);
        ss += __shfl_xor_sync(0xffffffffu, ss, o);
    }
    __shared__ float sh_s[8], sh_ss[8];
    int w = threadIdx.x >> 5, l = threadIdx.x & 31;
    if (l == 0) { sh_s[w] = s; sh_ss[w] = ss; }
    __syncthreads();
    if (threadIdx.x == 0) {
        float a = 0.f, b = 0.f;
        #pragma unroll
        for (int i = 0; i < 8; i++) { a += sh_s[i]; b += sh_ss[i]; }
        sum[c] = a; sumsq[c] = b;
    }
}

// ---------------------------------------------------------------------------
// Gamma MLP (coalesced, warp-per-row)
// ---------------------------------------------------------------------------
__global__ __launch_bounds__(1024) void gamma_kernel(
    const float* __restrict__ sum, const float* __restrict__ sumsq,
    const float* __restrict__ scale,
    const float* __restrict__ w1, const float* __restrict__ b1,
    const float* __restrict__ w2, const float* __restrict__ b2,
    float* __restrict__ fac)
{
    __shared__ float stats[CC];
    __shared__ float hbuf[HIDN];
    int tid = threadIdx.x, warp = tid >> 5, lane = tid & 31;
    if (tid < CC) stats[tid] = sum[tid] * (1.0f / PP);
    __syncthreads();
    for (int r = warp; r < HIDN; r += 32) {
        float a = 0.f;
        const float* wr = w1 + (size_t)r * CC;
        #pragma unroll
        for (int c = lane; c < CC; c += 32) a += stats[c] * wr[c];
        for (int o = 16; o; o >>= 1) a += __shfl_xor_sync(0xffffffffu, a, o);
        if (lane == 0) hbuf[r] = fmaxf(a + b1[r], 0.f);
    }
    __syncthreads();
    for (int r = warp; r < CC; r += 32) {
        float a = 0.f;
        const float* wr = w2 + (size_t)r * HIDN;
        #pragma unroll
        for (int c = lane; c < HIDN; c += 32) a += hbuf[c] * wr[c];
        for (int o = 16; o; o >>= 1) a += __shfl_xor_sync(0xffffffffu, a, o);
        if (lane == 0) {
            float gamma = 1.f / (1.f + expf(-(a + b2[r])));
            fac[r] = scale[r] * gamma * rsqrtf(sumsq[r] * (1.0f / PP) + 1e-6f);
        }
    }
}

// ---------------------------------------------------------------------------
// tf32 tensor-core GEMM (unchanged from R2)
// ---------------------------------------------------------------------------
__device__ __forceinline__ float gelu_f(float v) {
    return 0.5f * v * (1.f + erff(v * 0.70710678118654752f));
}
__device__ __forceinline__ unsigned f2tf(float f) {
    unsigned u; asm("cvt.rna.tf32.f32 %0, %1;" : "=r"(u) : "f"(f)); return u;
}
__device__ __forceinline__ void mma_tf32(float* c, const unsigned* a, const unsigned* b) {
    asm volatile(
        "mma.sync.aligned.m16n8k8.row.col.f32.tf32.tf32.f32 "
        "{%0,%1,%2,%3}, {%4,%5,%6,%7}, {%8,%9}, {%0,%1,%2,%3};"
        : "+f"(c[0]), "+f"(c[1]), "+f"(c[2]), "+f"(c[3])
        : "r"(a[0]), "r"(a[1]), "r"(a[2]), "r"(a[3]), "r"(b[0]), "r"(b[1]));
}

#define ASTR 136
#define BSTR 72

template<int MODE, int ASRC>
__global__ __launch_bounds__(256) void gemm_kernel(
    const float* __restrict__ A, const float* __restrict__ fac,
    const float* __restrict__ W, const float* __restrict__ bias,
    float* __restrict__ out, int N, int K,
    const float* __restrict__ res, float* __restrict__ out2)
{
    __shared__ float As[2][16 * ASTR];
    __shared__ float Ws[2][16 * BSTR];

    int bm = blockIdx.y * 128, bn = blockIdx.x * 64;
    int tid = threadIdx.x;
    int warp = tid >> 5, lane = tid & 31;
    int warp_m = warp & 3, warp_n = warp >> 2;
    int lq = lane & 3, l4 = lane >> 2;

    float acc[2][4][4];
    #pragma unroll
    for (int i = 0; i < 2; i++)
        #pragma unroll
        for (int j = 0; j < 4; j++)
            #pragma unroll
            for (int e = 0; e < 4; e++) acc[i][j][e] = 0.f;

    float4 ra[2], rb;
    int nPanels = K / 16;

    auto ldg_panel = [&](int p) {
        int k0 = p * 16;
        if (ASRC == 0) {
            #pragma unroll
            for (int u = 0; u < 2; u++) {
                int t = tid + u * 256;
                int m = t & 127, kc = t >> 7;
                ra[u] = *(const float4*)(A + (size_t)(bm + m) * K + k0 + kc * 4);
            }
        } else {
            #pragma unroll
            for (int u = 0; u < 2; u++) {
                int t = tid + u * 256;
                int mq = t & 31, k = t >> 5;
                float4 v = *(const float4*)(A + (size_t)(k0 + k) * PP + bm + mq * 4);
                float f = fac[k0 + k];
                v.x *= f; v.y *= f; v.z *= f; v.w *= f;
                ra[u] = v;
            }
        }
        int n = tid & 63, kc = tid >> 6;
        rb = *(const float4*)(W + (size_t)(bn + n) * K + k0 + kc * 4);
    };

    auto sts_panel = [&](int buf) {
        if (ASRC == 0) {
            #pragma unroll
            for (int u = 0; u < 2; u++) {
                int t = tid + u * 256;
                int m = t & 127, kc = t >> 7;
                float* dst = &As[buf][(kc * 4) * ASTR + m];
                dst[0 * ASTR] = __uint_as_float(f2tf(ra[u].x));
                dst[1 * ASTR] = __uint_as_float(f2tf(ra[u].y));
                dst[2 * ASTR] = __uint_as_float(f2tf(ra[u].z));
                dst[3 * ASTR] = __uint_as_float(f2tf(ra[u].w));
            }
        } else {
            #pragma unroll
            for (int u = 0; u < 2; u++) {
                int t = tid + u * 256;
                int mq = t & 31, k = t >> 5;
                float* dst = &As[buf][k * ASTR + mq * 4];
                dst[0] = __uint_as_float(f2tf(ra[u].x));
                dst[1] = __uint_as_float(f2tf(ra[u].y));
                dst[2] = __uint_as_float(f2tf(ra[u].z));
                dst[3] = __uint_as_float(f2tf(ra[u].w));
            }
        }
        int n = tid & 63, kc = tid >> 6;
        float* dst = &Ws[buf][(kc * 4) * BSTR + n];
        dst[0 * BSTR] = __uint_as_float(f2tf(rb.x));
        dst[1 * BSTR] = __uint_as_float(f2tf(rb.y));
        dst[2 * BSTR] = __uint_as_float(f2tf(rb.z));
        dst[3 * BSTR] = __uint_as_float(f2tf(rb.w));
    };

    auto compute = [&](int buf) {
        const float* as = As[buf];
        const float* ws = Ws[buf];
        #pragma unroll
        for (int ks = 0; ks < 2; ks++) {
            int kb = ks * 8;
            unsigned af[2][4];
            #pragma unroll
            for (int mt = 0; mt < 2; mt++) {
                int m0 = warp_m * 32 + mt * 16 + l4;
                const float* p = as + (kb + lq) * ASTR + m0;
                af[mt][0] = __float_as_uint(p[0]);
                af[mt][1] = __float_as_uint(p[8]);
                af[mt][2] = __float_as_uint(p[4 * ASTR]);
                af[mt][3] = __float_as_uint(p[4 * ASTR + 8]);
            }
            unsigned bf[4][2];
            #pragma unroll
            for (int nt = 0; nt < 4; nt++) {
                int n0 = warp_n * 32 + nt * 8 + l4;
                const float* p = ws + (kb + lq) * BSTR + n0;
                bf[nt][0] = __float_as_uint(p[0]);
                bf[nt][1] = __float_as_uint(p[4 * BSTR]);
            }
            #pragma unroll
            for (int mt = 0; mt < 2; mt++)
                #pragma unroll
                for (int nt = 0; nt < 4; nt++)
                    mma_tf32(acc[mt][nt], af[mt], bf[nt]);
        }
    };

    ldg_panel(0);
    sts_panel(0);
    __syncthreads();
    for (int p = 0; p < nPanels; p++) {
        if (p + 1 < nPanels) ldg_panel(p + 1);
        compute(p & 1);
        if (p + 1 < nPanels) { sts_panel((p + 1) & 1); __syncthreads(); }
    }

    #pragma unroll
    for (int mt = 0; mt < 2; mt++) {
        int r0 = bm + warp_m * 32 + mt * 16 + l4;
        #pragma unroll
        for (int nt = 0; nt < 4; nt++) {
            int c0 = bn + warp_n * 32 + nt * 8 + lq * 2;
            #pragma unroll
            for (int e = 0; e < 4; e++) {
                int m = r0 + (e >> 1) * 8;
                int n = c0 + (e & 1);
                float v = acc[mt][nt][e] + bias[n];
                if constexpr (MODE == 0) {
                    out[(size_t)m * N + n] = v;
                } else if constexpr (MODE == 1) {
                    v += res[(size_t)n * PP + m];
                    out[(size_t)m * N + n] = v;
                    out2[(size_t)n * PP + m] = v;
                } else if constexpr (MODE == 2) {
                    out[(size_t)m * N + n] = gelu_f(v);
                } else {
                    v += res[(size_t)m * N + n];
                    out[(size_t)n * PP + m] = v;
                }
            }
        }
    }
}

// ---------------------------------------------------------------------------
// Tensor-core 3D neighborhood attention.
// Block = (4x4x4 query tile, head), 256 threads (8 warps = 4 m x 2 n-halves).
// S = Q[64x32] @ K_halo[512x32]^T via fp16 mma.m16n8k16, per-query window
// mask -> exp (no max subtraction: |scores| << 80), rowsum, then
// O = P @ V_halo with P passed register-to-register (accum layout == A-frag
// layout). fp16 operands, fp32 accumulation throughout.
// ---------------------------------------------------------------------------
// smem layout (bytes):
//   K_s : [512][40] half   ->  40960   (pad 40: conflict-free B-frag loads)
//   V_t : [32][520] half   ->  33280   (transposed; 520%64==8 -> conflict-free)
//   Q_s : [64][40]  half   ->   5120
//   O0  : [64][33]  float  ->   8448   (warp_n=0 partial)
//   O1  : [64][33]  float  ->   8448   (warp_n=1 partial)
//   rsum: [2][64]   float  ->    512
#define ATTN_SMEM_BYTES (40960 + 33280 + 5120 + 8448 + 8448 + 512)

__device__ __forceinline__ void mma_fp16(float* c, const unsigned* a, unsigned b0, unsigned b1) {
    asm volatile(
        "mma.sync.aligned.m16n8k16.row.col.f32.f16.f16.f32 "
        "{%0,%1,%2,%3}, {%4,%5,%6,%7}, {%8,%9}, {%0,%1,%2,%3};"
        : "+f"(c[0]), "+f"(c[1]), "+f"(c[2]), "+f"(c[3])
        : "r"(a[0]), "r"(a[1]), "r"(a[2]), "r"(a[3]), "r"(b0), "r"(b1));
}
__device__ __forceinline__ unsigned pack_h2(float a, float b) {
    __half2 h = __floats2half2_rn(a, b);
    return *(unsigned*)&h;
}

__global__ __launch_bounds__(256, 2) void attn_mma_kernel(
    const float* __restrict__ qkv, float* __restrict__ attn_out)
{
    extern __shared__ char smem_raw[];
    __half* K_s = (__half*)smem_raw;
    __half* V_t = (__half*)(smem_raw + 40960);
    __half* Q_s = (__half*)(smem_raw + 74240);
    float*  O0  = (float*)(smem_raw + 79360);
    float*  O1  = (float*)(smem_raw + 87808);
    float*  rsum = (float*)(smem_raw + 96256);

    int tile = blockIdx.x, head = blockIdx.y;
    int td0 = (tile >> 4) * 4, th0 = ((tile >> 2) & 3) * 4, tw0 = (tile & 3) * 4;
    int hb_d = min(max(td0 - 2, 0), 8);
    int hb_h = min(max(th0 - 2, 0), 8);
    int hb_w = min(max(tw0 - 2, 0), 8);

    int tid = threadIdx.x;

    // ---- stage K (row-major) and V (transposed) halos, fp32 -> fp16 ----
    #pragma unroll 4
    for (int it = 0; it < 32; ++it) {
        int idx = tid + it * 256;            // 0..8191: (pos n, float2-chunk jp)
        int n = idx >> 4, jp = idx & 15;
        int d = hb_d + (n >> 6), h = hb_h + ((n >> 3) & 7), w = hb_w + (n & 7);
        size_t gb = (size_t)((d * 16 + h) * 16 + w) * NQKV + head * 32 + jp * 2;
        float2 kv = *(const float2*)(qkv + gb + 192);
        *(__half2*)(K_s + n * 40 + jp * 2) = __floats2half2_rn(kv.x, kv.y);
        float2 vv = *(const float2*)(qkv + gb + 384);
        V_t[(jp * 2)     * 520 + n] = __float2half_rn(vv.x);
        V_t[(jp * 2 + 1) * 520 + n] = __float2half_rn(vv.y);
    }
    const float scale_qk = 0.17677669529663687f;  // 32^-0.5, folded into Q
    #pragma unroll
    for (int it = 0; it < 4; ++it) {
        int idx = tid + it * 256;            // 0..1023
        int m = idx >> 4, jp = idx & 15;
        int gd = td0 + (m >> 4), gh = th0 + ((m >> 2) & 3), gw = tw0 + (m & 3);
        size_t gb = (size_t)((gd * 16 + gh) * 16 + gw) * NQKV + head * 32 + jp * 2;
        float2 qv = *(const float2*)(qkv + gb);
        *(__half2*)(Q_s + m * 40 + jp * 2) =
            __floats2half2_rn(qv.x * scale_qk, qv.y * scale_qk);
    }
    __syncthreads();

    int warp = tid >> 5, lane = tid & 31;
    int warp_m = warp & 3, warp_n = warp >> 2;
    int g = lane >> 2, q = lane & 3;
    int r0 = warp_m * 16 + g;
    int r1 = r0 + 8;

    // per-row window lows in halo coords (each in [0,3]; window width 5)
    int ld0, lh0, lw0, ld1, lh1, lw1;
    {
        int qd = r0 >> 4, qh = (r0 >> 2) & 3, qw = r0 & 3;
        ld0 = min(max(td0 + qd - 2, 0), 11) - hb_d;
        lh0 = min(max(th0 + qh - 2, 0), 11) - hb_h;
        lw0 = min(max(tw0 + qw - 2, 0), 11) - hb_w;
        qd = r1 >> 4; qh = (r1 >> 2) & 3; qw = r1 & 3;
        ld1 = min(max(td0 + qd - 2, 0), 11) - hb_d;
        lh1 = min(max(th0 + qh - 2, 0), 11) - hb_h;
        lw1 = min(max(tw0 + qw - 2, 0), 11) - hb_w;
    }
    // per-thread w-column validity (cols 2q, 2q+1) -- fixed across all tiles
    bool wv00 = (2*q   >= lw0) && (2*q   < lw0 + 5);
    bool wv01 = (2*q+1 >= lw0) && (2*q+1 < lw0 + 5);
    bool wv10 = (2*q   >= lw1) && (2*q   < lw1 + 5);
    bool wv11 = (2*q+1 >= lw1) && (2*q+1 < lw1 + 5);

    // Q A-fragments (2 k-chunks of 16)
    unsigned qa[2][4];
    #pragma unroll
    for (int kc = 0; kc < 2; ++kc) {
        const __half* qp = Q_s + kc * 16 + 2 * q;
        qa[kc][0] = *(const unsigned*)(qp + r0 * 40);
        qa[kc][1] = *(const unsigned*)(qp + r1 * 40);
        qa[kc][2] = *(const unsigned*)(qp + r0 * 40 + 8);
        qa[kc][3] = *(const unsigned*)(qp + r1 * 40 + 8);
    }

    float oacc[4][4];
    #pragma unroll
    for (int i = 0; i < 4; i++)
        #pragma unroll
        for (int e = 0; e < 4; e++) oacc[i][e] = 0.f;
    float rs0 = 0.f, rs1 = 0.f;

    #pragma unroll
    for (int chunk = 0; chunk < 4; ++chunk) {
        int J0 = warp_n * 32 + chunk * 8;    // first n-tile (8 halo cols each)

        // ---- S = Q K^T over 8 n-tiles ----
        float c[8][4];
        #pragma unroll
        for (int j = 0; j < 8; j++)
            #pragma unroll
            for (int e = 0; e < 4; e++) c[j][e] = 0.f;
        #pragma unroll
        for (int j = 0; j < 8; ++j) {
            const __half* kp = K_s + (size_t)(8 * (J0 + j) + g) * 40 + 2 * q;
            #pragma unroll
            for (int kc = 0; kc < 2; ++kc) {
                unsigned b0 = *(const unsigned*)(kp + kc * 16);
                unsigned b1 = *(const unsigned*)(kp + kc * 16 + 8);
                mma_fp16(c[j], qa[kc], b0, b1);
            }
        }

        // ---- mask + exp + pack P (fp16) ----
        unsigned plo[8], phi[8];
        #pragma unroll
        for (int j = 0; j < 8; ++j) {
            int J = J0 + j;
            int d = J >> 3, h = J & 7;       // all 8 cols of tile share (d,h)
            bool dh0 = (d >= ld0) && (d < ld0 + 5) && (h >= lh0) && (h < lh0 + 5);
            bool dh1 = (d >= ld1) && (d < ld1 + 5) && (h >= lh1) && (h < lh1 + 5);
            float e0 = (dh0 && wv00) ? __expf(c[j][0]) : 0.f;
            float e1 = (dh0 && wv01) ? __expf(c[j][1]) : 0.f;
            float e2 = (dh1 && wv10) ? __expf(c[j][2]) : 0.f;
            float e3 = (dh1 && wv11) ? __expf(c[j][3]) : 0.f;
            rs0 += e0 + e1;
            rs1 += e2 + e3;
            plo[j] = pack_h2(e0, e1);
            phi[j] = pack_h2(e2, e3);
        }

        // ---- O += P @ V over this 64-col chunk (4 k16 sub-chunks) ----
        #pragma unroll
        for (int kk = 0; kk < 4; ++kk) {
            unsigned pa[4] = { plo[2*kk], phi[2*kk], plo[2*kk+1], phi[2*kk+1] };
            int kb = J0 * 8 + kk * 16 + 2 * q;
            #pragma unroll
            for (int ot = 0; ot < 4; ++ot) {
                const __half* vp = V_t + (size_t)(ot * 8 + g) * 520 + kb;
                unsigned b0 = *(const unsigned*)vp;
                unsigned b1 = *(const unsigned*)(vp + 8);
                mma_fp16(oacc[ot], pa, b0, b1);
            }
        }
    }

    // ---- rowsum quad-reduce ----
    rs0 += __shfl_xor_sync(0xffffffffu, rs0, 1);
    rs0 += __shfl_xor_sync(0xffffffffu, rs0, 2);
    rs1 += __shfl_xor_sync(0xffffffffu, rs1, 1);
    rs1 += __shfl_xor_sync(0xffffffffu, rs1, 2);
    if (q == 0) {
        rsum[warp_n * 64 + r0] = rs0;
        rsum[warp_n * 64 + r1] = rs1;
    }

    // ---- O partials to smem ----
    float* Obuf = warp_n ? O1 : O0;
    #pragma unroll
    for (int ot = 0; ot < 4; ++ot) {
        Obuf[r0 * 33 + ot * 8 + 2 * q]     = oacc[ot][0];
        Obuf[r0 * 33 + ot * 8 + 2 * q + 1] = oacc[ot][1];
        Obuf[r1 * 33 + ot * 8 + 2 * q]     = oacc[ot][2];
        Obuf[r1 * 33 + ot * 8 + 2 * q + 1] = oacc[ot][3];
    }
    __syncthreads();

    // ---- combine halves, normalize, coalesced write ----
    #pragma unroll
    for (int i = tid; i < 64 * 32; i += 256) {
        int row = i >> 5, ch = i & 31;
        float inv = 1.f / (rsum[row] + rsum[64 + row]);
        float v = (O0[row * 33 + ch] + O1[row * 33 + ch]) * inv;
        int gd = td0 + (row >> 4), gh = th0 + ((row >> 2) & 3), gw = tw0 + (row & 3);
        attn_out[(size_t)((gd * 16 + gh) * 16 + gw) * CC + head * 32 + ch] = v;
    }
}

// ---------------------------------------------------------------------------
extern "C" void kernel_launch(void* const* d_in, const int* in_sizes, int n_in,
                              void* d_out, int out_size)
{
    const float* x      = (const float*)d_in[0];
    const float* scale1 = (const float*)d_in[1];
    const float* n1_w1  = (const float*)d_in[2];
    const float* n1_b1  = (const float*)d_in[3];
    const float* n1_w2  = (const float*)d_in[4];
    const float* n1_b2  = (const float*)d_in[5];
    const float* qkv_w  = (const float*)d_in[6];
    const float* qkv_b  = (const float*)d_in[7];
    const float* proj_w = (const float*)d_in[8];
    const float* proj_b = (const float*)d_in[9];
    const float* scale2 = (const float*)d_in[10];
    const float* n2_w1  = (const float*)d_in[11];
    const float* n2_b1  = (const float*)d_in[12];
    const float* n2_w2  = (const float*)d_in[13];
    const float* n2_b2  = (const float*)d_in[14];
    const float* mlp_w1 = (const float*)d_in[15];
    const float* mlp_b1 = (const float*)d_in[16];
    const float* mlp_w2 = (const float*)d_in[17];
    const float* mlp_b2 = (const float*)d_in[18];
    float* out = (float*)d_out;

    float* S = nullptr;
    cudaGetSymbolAddress((void**)&S, g_scratch);
    float* g_sum   = S + O_SUM;
    float* g_sumsq = S + O_SUMSQ;
    float* g_fac   = S + O_FAC;
    float* g_qkv   = S + O_QKV;
    float* g_attn  = S + O_ATTN;
    float* g_x2t   = S + O_X2T;
    float* g_x2c   = S + O_X2C;
    float* g_m1    = S + O_M1;

    cudaFuncSetAttribute(attn_mma_kernel, cudaFuncAttributeMaxDynamicSharedMemorySize, ATTN_SMEM_BYTES);

    // --- block 1: ada_rmsnorm(x) factors ---
    reduce_kernel<<<CC, 256>>>(x, g_sum, g_sumsq);
    gamma_kernel<<<1, 1024>>>(g_sum, g_sumsq, scale1, n1_w1, n1_b1, n1_w2, n1_b2, g_fac);

    // --- QKV projection (norm fused into A-stage) ---
    gemm_kernel<0, 1><<<dim3(NQKV/64, PP/128), 256>>>(x, g_fac, qkv_w, qkv_b, g_qkv, NQKV, CC, nullptr, nullptr);

    // --- neighborhood attention (tensor cores) ---
    attn_mma_kernel<<<dim3(64, 6), 256, ATTN_SMEM_BYTES>>>(g_qkv, g_attn);

    // --- output projection + residual (both layouts) ---
    gemm_kernel<1, 0><<<dim3(CC/64, PP/128), 256>>>(g_attn, nullptr, proj_w, proj_b, g_x2t, CC, CC, x, g_x2c);

    // --- block 2: ada_rmsnorm(x2) factors ---
    reduce_kernel<<<CC, 256>>>(g_x2c, g_sum, g_sumsq);
    gamma_kernel<<<1, 1024>>>(g_sum, g_sumsq, scale2, n2_w1, n2_b1, n2_w2, n2_b2, g_fac);

    // --- MLP (norm fused into A-stage of first GEMM) ---
    gemm_kernel<2, 1><<<dim3(MLPH/64, PP/128), 256>>>(g_x2c, g_fac, mlp_w1, mlp_b1, g_m1, MLPH, CC, nullptr, nullptr);
    gemm_kernel<3, 0><<<dim3(CC/64, PP/128), 256>>>(g_m1, nullptr, mlp_w2, mlp_b2, out, CC, MLPH, g_x2t, nullptr);
}

// round 13
// speedup vs baseline: 1.0288x; 1.0275x over previous
#include <cuda_runtime.h>
#include <cuda_fp16.h>
#include <math.h>

#define PP   4096   // D*H*W
#define CC   192
#define HIDN 384
#define MLPH 768
#define NQKV 576

static constexpr size_t O_SUM   = 0;
static constexpr size_t O_SUMSQ = 256;
static constexpr size_t O_FAC   = 512;
static constexpr size_t O_QKV   = 1024;
static constexpr size_t O_ATTN  = O_QKV  + (size_t)PP*NQKV;
static constexpr size_t O_X2T   = O_ATTN + (size_t)PP*CC;
static constexpr size_t O_X2C   = O_X2T  + (size_t)PP*CC;
static constexpr size_t O_M1    = O_X2C  + (size_t)PP*CC;
static constexpr size_t SCRATCH_TOTAL = O_M1 + (size_t)PP*MLPH;

__device__ float g_scratch[SCRATCH_TOTAL];

// ---------------------------------------------------------------------------
// Per-channel sum & sum-of-squares over 4096 contiguous spatial elements
// ---------------------------------------------------------------------------
__global__ __launch_bounds__(256) void reduce_kernel(
    const float* __restrict__ xc, float* __restrict__ sum, float* __restrict__ sumsq)
{
    int c = blockIdx.x;
    const float4* xr = (const float4*)(xc + (size_t)c * PP);
    float s = 0.f, ss = 0.f;
    for (int i = threadIdx.x; i < PP/4; i += 256) {
        float4 v = xr[i];
        s  += v.x + v.y + v.z + v.w;
        ss += v.x*v.x + v.y*v.y + v.z*v.z + v.w*v.w;
    }
    for (int o = 16; o; o >>= 1) {
        s  += __shfl_xor_sync(0xffffffffu, s,  o);
        ss += __shfl_xor_sync(0xffffffffu, ss, o);
    }
    __shared__ float sh_s[8], sh_ss[8];
    int w = threadIdx.x >> 5, l = threadIdx.x & 31;
    if (l == 0) { sh_s[w] = s; sh_ss[w] = ss; }
    __syncthreads();
    if (threadIdx.x == 0) {
        float a = 0.f, b = 0.f;
        #pragma unroll
        for (int i = 0; i < 8; i++) { a += sh_s[i]; b += sh_ss[i]; }
        sum[c] = a; sumsq[c] = b;
    }
}

// ---------------------------------------------------------------------------
// Gamma MLP (coalesced, warp-per-row)
// ---------------------------------------------------------------------------
__global__ __launch_bounds__(1024) void gamma_kernel(
    const float* __restrict__ sum, const float* __restrict__ sumsq,
    const float* __restrict__ scale,
    const float* __restrict__ w1, const float* __restrict__ b1,
    const float* __restrict__ w2, const float* __restrict__ b2,
    float* __restrict__ fac)
{
    __shared__ float stats[CC];
    __shared__ float hbuf[HIDN];
    int tid = threadIdx.x, warp = tid >> 5, lane = tid & 31;
    if (tid < CC) stats[tid] = sum[tid] * (1.0f / PP);
    __syncthreads();
    for (int r = warp; r < HIDN; r += 32) {
        float a = 0.f;
        const float* wr = w1 + (size_t)r * CC;
        #pragma unroll
        for (int c = lane; c < CC; c += 32) a += stats[c] * wr[c];
        for (int o = 16; o; o >>= 1) a += __shfl_xor_sync(0xffffffffu, a, o);
        if (lane == 0) hbuf[r] = fmaxf(a + b1[r], 0.f);
    }
    __syncthreads();
    for (int r = warp; r < CC; r += 32) {
        float a = 0.f;
        const float* wr = w2 + (size_t)r * HIDN;
        #pragma unroll
        for (int c = lane; c < HIDN; c += 32) a += hbuf[c] * wr[c];
        for (int o = 16; o; o >>= 1) a += __shfl_xor_sync(0xffffffffu, a, o);
        if (lane == 0) {
            float gamma = 1.f / (1.f + expf(-(a + b2[r])));
            fac[r] = scale[r] * gamma * rsqrtf(sumsq[r] * (1.0f / PP) + 1e-6f);
        }
    }
}

// ---------------------------------------------------------------------------
// tf32 tensor-core GEMM (unchanged from R2)
// ---------------------------------------------------------------------------
__device__ __forceinline__ float gelu_f(float v) {
    return 0.5f * v * (1.f + erff(v * 0.70710678118654752f));
}
__device__ __forceinline__ unsigned f2tf(float f) {
    unsigned u; asm("cvt.rna.tf32.f32 %0, %1;" : "=r"(u) : "f"(f)); return u;
}
__device__ __forceinline__ void mma_tf32(float* c, const unsigned* a, const unsigned* b) {
    asm volatile(
        "mma.sync.aligned.m16n8k8.row.col.f32.tf32.tf32.f32 "
        "{%0,%1,%2,%3}, {%4,%5,%6,%7}, {%8,%9}, {%0,%1,%2,%3};"
        : "+f"(c[0]), "+f"(c[1]), "+f"(c[2]), "+f"(c[3])
        : "r"(a[0]), "r"(a[1]), "r"(a[2]), "r"(a[3]), "r"(b[0]), "r"(b[1]));
}

#define ASTR 136
#define BSTR 72

template<int MODE, int ASRC>
__global__ __launch_bounds__(256) void gemm_kernel(
    const float* __restrict__ A, const float* __restrict__ fac,
    const float* __restrict__ W, const float* __restrict__ bias,
    float* __restrict__ out, int N, int K,
    const float* __restrict__ res, float* __restrict__ out2)
{
    __shared__ float As[2][16 * ASTR];
    __shared__ float Ws[2][16 * BSTR];

    int bm = blockIdx.y * 128, bn = blockIdx.x * 64;
    int tid = threadIdx.x;
    int warp = tid >> 5, lane = tid & 31;
    int warp_m = warp & 3, warp_n = warp >> 2;
    int lq = lane & 3, l4 = lane >> 2;

    float acc[2][4][4];
    #pragma unroll
    for (int i = 0; i < 2; i++)
        #pragma unroll
        for (int j = 0; j < 4; j++)
            #pragma unroll
            for (int e = 0; e < 4; e++) acc[i][j][e] = 0.f;

    float4 ra[2], rb;
    int nPanels = K / 16;

    auto ldg_panel = [&](int p) {
        int k0 = p * 16;
        if (ASRC == 0) {
            #pragma unroll
            for (int u = 0; u < 2; u++) {
                int t = tid + u * 256;
                int m = t & 127, kc = t >> 7;
                ra[u] = *(const float4*)(A + (size_t)(bm + m) * K + k0 + kc * 4);
            }
        } else {
            #pragma unroll
            for (int u = 0; u < 2; u++) {
                int t = tid + u * 256;
                int mq = t & 31, k = t >> 5;
                float4 v = *(const float4*)(A + (size_t)(k0 + k) * PP + bm + mq * 4);
                float f = fac[k0 + k];
                v.x *= f; v.y *= f; v.z *= f; v.w *= f;
                ra[u] = v;
            }
        }
        int n = tid & 63, kc = tid >> 6;
        rb = *(const float4*)(W + (size_t)(bn + n) * K + k0 + kc * 4);
    };

    auto sts_panel = [&](int buf) {
        if (ASRC == 0) {
            #pragma unroll
            for (int u = 0; u < 2; u++) {
                int t = tid + u * 256;
                int m = t & 127, kc = t >> 7;
                float* dst = &As[buf][(kc * 4) * ASTR + m];
                dst[0 * ASTR] = __uint_as_float(f2tf(ra[u].x));
                dst[1 * ASTR] = __uint_as_float(f2tf(ra[u].y));
                dst[2 * ASTR] = __uint_as_float(f2tf(ra[u].z));
                dst[3 * ASTR] = __uint_as_float(f2tf(ra[u].w));
            }
        } else {
            #pragma unroll
            for (int u = 0; u < 2; u++) {
                int t = tid + u * 256;
                int mq = t & 31, k = t >> 5;
                float* dst = &As[buf][k * ASTR + mq * 4];
                dst[0] = __uint_as_float(f2tf(ra[u].x));
                dst[1] = __uint_as_float(f2tf(ra[u].y));
                dst[2] = __uint_as_float(f2tf(ra[u].z));
                dst[3] = __uint_as_float(f2tf(ra[u].w));
            }
        }
        int n = tid & 63, kc = tid >> 6;
        float* dst = &Ws[buf][(kc * 4) * BSTR + n];
        dst[0 * BSTR] = __uint_as_float(f2tf(rb.x));
        dst[1 * BSTR] = __uint_as_float(f2tf(rb.y));
        dst[2 * BSTR] = __uint_as_float(f2tf(rb.z));
        dst[3 * BSTR] = __uint_as_float(f2tf(rb.w));
    };

    auto compute = [&](int buf) {
        const float* as = As[buf];
        const float* ws = Ws[buf];
        #pragma unroll
        for (int ks = 0; ks < 2; ks++) {
            int kb = ks * 8;
            unsigned af[2][4];
            #pragma unroll
            for (int mt = 0; mt < 2; mt++) {
                int m0 = warp_m * 32 + mt * 16 + l4;
                const float* p = as + (kb + lq) * ASTR + m0;
                af[mt][0] = __float_as_uint(p[0]);
                af[mt][1] = __float_as_uint(p[8]);
                af[mt][2] = __float_as_uint(p[4 * ASTR]);
                af[mt][3] = __float_as_uint(p[4 * ASTR + 8]);
            }
            unsigned bf[4][2];
            #pragma unroll
            for (int nt = 0; nt < 4; nt++) {
                int n0 = warp_n * 32 + nt * 8 + l4;
                const float* p = ws + (kb + lq) * BSTR + n0;
                bf[nt][0] = __float_as_uint(p[0]);
                bf[nt][1] = __float_as_uint(p[4 * BSTR]);
            }
            #pragma unroll
            for (int mt = 0; mt < 2; mt++)
                #pragma unroll
                for (int nt = 0; nt < 4; nt++)
                    mma_tf32(acc[mt][nt], af[mt], bf[nt]);
        }
    };

    ldg_panel(0);
    sts_panel(0);
    __syncthreads();
    for (int p = 0; p < nPanels; p++) {
        if (p + 1 < nPanels) ldg_panel(p + 1);
        compute(p & 1);
        if (p + 1 < nPanels) { sts_panel((p + 1) & 1); __syncthreads(); }
    }

    #pragma unroll
    for (int mt = 0; mt < 2; mt++) {
        int r0 = bm + warp_m * 32 + mt * 16 + l4;
        #pragma unroll
        for (int nt = 0; nt < 4; nt++) {
            int c0 = bn + warp_n * 32 + nt * 8 + lq * 2;
            #pragma unroll
            for (int e = 0; e < 4; e++) {
                int m = r0 + (e >> 1) * 8;
                int n = c0 + (e & 1);
                float v = acc[mt][nt][e] + bias[n];
                if constexpr (MODE == 0) {
                    out[(size_t)m * N + n] = v;
                } else if constexpr (MODE == 1) {
                    v += res[(size_t)n * PP + m];
                    out[(size_t)m * N + n] = v;
                    out2[(size_t)n * PP + m] = v;
                } else if constexpr (MODE == 2) {
                    out[(size_t)m * N + n] = gelu_f(v);
                } else {
                    v += res[(size_t)m * N + n];
                    out[(size_t)n * PP + m] = v;
                }
            }
        }
    }
}

// ---------------------------------------------------------------------------
// Tensor-core 3D neighborhood attention.
// Block = (4x4x4 query tile, head), 256 threads (8 warps = 4 m x 2 n-halves).
// S = Q[64x32] @ K_halo[512x32]^T via fp16 mma.m16n8k16, per-query window
// mask -> exp (no max subtraction: |scores| << 80), rowsum, then
// O = P @ V_halo with P passed register-to-register (accum layout == A-frag
// layout). fp16 operands, fp32 accumulation throughout.
// ---------------------------------------------------------------------------
// smem layout (bytes):
//   K_s : [512][40] half   ->  40960   (pad 40: conflict-free B-frag loads)
//   V_t : [32][520] half   ->  33280   (transposed; 520%64==8 -> conflict-free)
//   Q_s : [64][40]  half   ->   5120
//   O0  : [64][33]  float  ->   8448   (warp_n=0 partial)
//   O1  : [64][33]  float  ->   8448   (warp_n=1 partial)
//   rsum: [2][64]   float  ->    512
#define ATTN_SMEM_BYTES (40960 + 33280 + 5120 + 8448 + 8448 + 512)

__device__ __forceinline__ void mma_fp16(float* c, const unsigned* a, unsigned b0, unsigned b1) {
    asm volatile(
        "mma.sync.aligned.m16n8k16.row.col.f32.f16.f16.f32 "
        "{%0,%1,%2,%3}, {%4,%5,%6,%7}, {%8,%9}, {%0,%1,%2,%3};"
        : "+f"(c[0]), "+f"(c[1]), "+f"(c[2]), "+f"(c[3])
        : "r"(a[0]), "r"(a[1]), "r"(a[2]), "r"(a[3]), "r"(b0), "r"(b1));
}
__device__ __forceinline__ unsigned pack_h2(float a, float b) {
    __half2 h = __floats2half2_rn(a, b);
    return *(unsigned*)&h;
}

__global__ __launch_bounds__(256, 2) void attn_mma_kernel(
    const float* __restrict__ qkv, float* __restrict__ attn_out)
{
    extern __shared__ char smem_raw[];
    __half* K_s = (__half*)smem_raw;
    __half* V_t = (__half*)(smem_raw + 40960);
    __half* Q_s = (__half*)(smem_raw + 74240);
    float*  O0  = (float*)(smem_raw + 79360);
    float*  O1  = (float*)(smem_raw + 87808);
    float*  rsum = (float*)(smem_raw + 96256);

    int tile = blockIdx.x, head = blockIdx.y;
    int td0 = (tile >> 4) * 4, th0 = ((tile >> 2) & 3) * 4, tw0 = (tile & 3) * 4;
    int hb_d = min(max(td0 - 2, 0), 8);
    int hb_h = min(max(th0 - 2, 0), 8);
    int hb_w = min(max(tw0 - 2, 0), 8);

    int tid = threadIdx.x;

    // ---- stage K (row-major) and V (transposed) halos, fp32 -> fp16 ----
    #pragma unroll 4
    for (int it = 0; it < 32; ++it) {
        int idx = tid + it * 256;            // 0..8191: (pos n, float2-chunk jp)
        int n = idx >> 4, jp = idx & 15;
        int d = hb_d + (n >> 6), h = hb_h + ((n >> 3) & 7), w = hb_w + (n & 7);
        size_t gb = (size_t)((d * 16 + h) * 16 + w) * NQKV + head * 32 + jp * 2;
        float2 kv = *(const float2*)(qkv + gb + 192);
        *(__half2*)(K_s + n * 40 + jp * 2) = __floats2half2_rn(kv.x, kv.y);
        float2 vv = *(const float2*)(qkv + gb + 384);
        V_t[(jp * 2)     * 520 + n] = __float2half_rn(vv.x);
        V_t[(jp * 2 + 1) * 520 + n] = __float2half_rn(vv.y);
    }
    const float scale_qk = 0.17677669529663687f;  // 32^-0.5, folded into Q
    #pragma unroll
    for (int it = 0; it < 4; ++it) {
        int idx = tid + it * 256;            // 0..1023
        int m = idx >> 4, jp = idx & 15;
        int gd = td0 + (m >> 4), gh = th0 + ((m >> 2) & 3), gw = tw0 + (m & 3);
        size_t gb = (size_t)((gd * 16 + gh) * 16 + gw) * NQKV + head * 32 + jp * 2;
        float2 qv = *(const float2*)(qkv + gb);
        *(__half2*)(Q_s + m * 40 + jp * 2) =
            __floats2half2_rn(qv.x * scale_qk, qv.y * scale_qk);
    }
    __syncthreads();

    int warp = tid >> 5, lane = tid & 31;
    int warp_m = warp & 3, warp_n = warp >> 2;
    int g = lane >> 2, q = lane & 3;
    int r0 = warp_m * 16 + g;
    int r1 = r0 + 8;

    // per-row window lows in halo coords (each in [0,3]; window width 5)
    int ld0, lh0, lw0, ld1, lh1, lw1;
    {
        int qd = r0 >> 4, qh = (r0 >> 2) & 3, qw = r0 & 3;
        ld0 = min(max(td0 + qd - 2, 0), 11) - hb_d;
        lh0 = min(max(th0 + qh - 2, 0), 11) - hb_h;
        lw0 = min(max(tw0 + qw - 2, 0), 11) - hb_w;
        qd = r1 >> 4; qh = (r1 >> 2) & 3; qw = r1 & 3;
        ld1 = min(max(td0 + qd - 2, 0), 11) - hb_d;
        lh1 = min(max(th0 + qh - 2, 0), 11) - hb_h;
        lw1 = min(max(tw0 + qw - 2, 0), 11) - hb_w;
    }
    // per-thread w-column validity (cols 2q, 2q+1) -- fixed across all tiles
    bool wv00 = (2*q   >= lw0) && (2*q   < lw0 + 5);
    bool wv01 = (2*q+1 >= lw0) && (2*q+1 < lw0 + 5);
    bool wv10 = (2*q   >= lw1) && (2*q   < lw1 + 5);
    bool wv11 = (2*q+1 >= lw1) && (2*q+1 < lw1 + 5);

    // Q A-fragments (2 k-chunks of 16)
    unsigned qa[2][4];
    #pragma unroll
    for (int kc = 0; kc < 2; ++kc) {
        const __half* qp = Q_s + kc * 16 + 2 * q;
        qa[kc][0] = *(const unsigned*)(qp + r0 * 40);
        qa[kc][1] = *(const unsigned*)(qp + r1 * 40);
        qa[kc][2] = *(const unsigned*)(qp + r0 * 40 + 8);
        qa[kc][3] = *(const unsigned*)(qp + r1 * 40 + 8);
    }

    float oacc[4][4];
    #pragma unroll
    for (int i = 0; i < 4; i++)
        #pragma unroll
        for (int e = 0; e < 4; e++) oacc[i][e] = 0.f;
    float rs0 = 0.f, rs1 = 0.f;

    #pragma unroll
    for (int chunk = 0; chunk < 4; ++chunk) {
        int J0 = warp_n * 32 + chunk * 8;    // first n-tile (8 halo cols each)

        // ---- S = Q K^T over 8 n-tiles ----
        float c[8][4];
        #pragma unroll
        for (int j = 0; j < 8; j++)
            #pragma unroll
            for (int e = 0; e < 4; e++) c[j][e] = 0.f;
        #pragma unroll
        for (int j = 0; j < 8; ++j) {
            const __half* kp = K_s + (size_t)(8 * (J0 + j) + g) * 40 + 2 * q;
            #pragma unroll
            for (int kc = 0; kc < 2; ++kc) {
                unsigned b0 = *(const unsigned*)(kp + kc * 16);
                unsigned b1 = *(const unsigned*)(kp + kc * 16 + 8);
                mma_fp16(c[j], qa[kc], b0, b1);
            }
        }

        // ---- mask + exp + pack P (fp16) ----
        unsigned plo[8], phi[8];
        #pragma unroll
        for (int j = 0; j < 8; ++j) {
            int J = J0 + j;
            int d = J >> 3, h = J & 7;       // all 8 cols of tile share (d,h)
            bool dh0 = (d >= ld0) && (d < ld0 + 5) && (h >= lh0) && (h < lh0 + 5);
            bool dh1 = (d >= ld1) && (d < ld1 + 5) && (h >= lh1) && (h < lh1 + 5);
            float e0 = (dh0 && wv00) ? __expf(c[j][0]) : 0.f;
            float e1 = (dh0 && wv01) ? __expf(c[j][1]) : 0.f;
            float e2 = (dh1 && wv10) ? __expf(c[j][2]) : 0.f;
            float e3 = (dh1 && wv11) ? __expf(c[j][3]) : 0.f;
            rs0 += e0 + e1;
            rs1 += e2 + e3;
            plo[j] = pack_h2(e0, e1);
            phi[j] = pack_h2(e2, e3);
        }

        // ---- O += P @ V over this 64-col chunk (4 k16 sub-chunks) ----
        #pragma unroll
        for (int kk = 0; kk < 4; ++kk) {
            unsigned pa[4] = { plo[2*kk], phi[2*kk], plo[2*kk+1], phi[2*kk+1] };
            int kb = J0 * 8 + kk * 16 + 2 * q;
            #pragma unroll
            for (int ot = 0; ot < 4; ++ot) {
                const __half* vp = V_t + (size_t)(ot * 8 + g) * 520 + kb;
                unsigned b0 = *(const unsigned*)vp;
                unsigned b1 = *(const unsigned*)(vp + 8);
                mma_fp16(oacc[ot], pa, b0, b1);
            }
        }
    }

    // ---- rowsum quad-reduce ----
    rs0 += __shfl_xor_sync(0xffffffffu, rs0, 1);
    rs0 += __shfl_xor_sync(0xffffffffu, rs0, 2);
    rs1 += __shfl_xor_sync(0xffffffffu, rs1, 1);
    rs1 += __shfl_xor_sync(0xffffffffu, rs1, 2);
    if (q == 0) {
        rsum[warp_n * 64 + r0] = rs0;
        rsum[warp_n * 64 + r1] = rs1;
    }

    // ---- O partials to smem ----
    float* Obuf = warp_n ? O1 : O0;
    #pragma unroll
    for (int ot = 0; ot < 4; ++ot) {
        Obuf[r0 * 33 + ot * 8 + 2 * q]     = oacc[ot][0];
        Obuf[r0 * 33 + ot * 8 + 2 * q + 1] = oacc[ot][1];
        Obuf[r1 * 33 + ot * 8 + 2 * q]     = oacc[ot][2];
        Obuf[r1 * 33 + ot * 8 + 2 * q + 1] = oacc[ot][3];
    }
    __syncthreads();

    // ---- combine halves, normalize, coalesced write ----
    #pragma unroll
    for (int i = tid; i < 64 * 32; i += 256) {
        int row = i >> 5, ch = i & 31;
        float inv = 1.f / (rsum[row] + rsum[64 + row]);
        float v = (O0[row * 33 + ch] + O1[row * 33 + ch]) * inv;
        int gd = td0 + (row >> 4), gh = th0 + ((row >> 2) & 3), gw = tw0 + (row & 3);
        attn_out[(size_t)((gd * 16 + gh) * 16 + gw) * CC + head * 32 + ch] = v;
    }
}

// ---------------------------------------------------------------------------
extern "C" void kernel_launch(void* const* d_in, const int* in_sizes, int n_in,
                              void* d_out, int out_size)
{
    const float* x      = (const float*)d_in[0];
    const float* scale1 = (const float*)d_in[1];
    const float* n1_w1  = (const float*)d_in[2];
    const float* n1_b1  = (const float*)d_in[3];
    const float* n1_w2  = (const float*)d_in[4];
    const float* n1_b2  = (const float*)d_in[5];
    const float* qkv_w  = (const float*)d_in[6];
    const float* qkv_b  = (const float*)d_in[7];
    const float* proj_w = (const float*)d_in[8];
    const float* proj_b = (const float*)d_in[9];
    const float* scale2 = (const float*)d_in[10];
    const float* n2_w1  = (const float*)d_in[11];
    const float* n2_b1  = (const float*)d_in[12];
    const float* n2_w2  = (const float*)d_in[13];
    const float* n2_b2  = (const float*)d_in[14];
    const float* mlp_w1 = (const float*)d_in[15];
    const float* mlp_b1 = (const float*)d_in[16];
    const float* mlp_w2 = (const float*)d_in[17];
    const float* mlp_b2 = (const float*)d_in[18];
    float* out = (float*)d_out;

    float* S = nullptr;
    cudaGetSymbolAddress((void**)&S, g_scratch);
    float* g_sum   = S + O_SUM;
    float* g_sumsq = S + O_SUMSQ;
    float* g_fac   = S + O_FAC;
    float* g_qkv   = S + O_QKV;
    float* g_attn  = S + O_ATTN;
    float* g_x2t   = S + O_X2T;
    float* g_x2c   = S + O_X2C;
    float* g_m1    = S + O_M1;

    cudaFuncSetAttribute(attn_mma_kernel, cudaFuncAttributeMaxDynamicSharedMemorySize, ATTN_SMEM_BYTES);

    // --- block 1: ada_rmsnorm(x) factors ---
    reduce_kernel<<<CC, 256>>>(x, g_sum, g_sumsq);
    gamma_kernel<<<1, 1024>>>(g_sum, g_sumsq, scale1, n1_w1, n1_b1, n1_w2, n1_b2, g_fac);

    // --- QKV projection (norm fused into A-stage) ---
    gemm_kernel<0, 1><<<dim3(NQKV/64, PP/128), 256>>>(x, g_fac, qkv_w, qkv_b, g_qkv, NQKV, CC, nullptr, nullptr);

    // --- neighborhood attention (tensor cores) ---
    attn_mma_kernel<<<dim3(64, 6), 256, ATTN_SMEM_BYTES>>>(g_qkv, g_attn);

    // --- output projection + residual (both layouts) ---
    gemm_kernel<1, 0><<<dim3(CC/64, PP/128), 256>>>(g_attn, nullptr, proj_w, proj_b, g_x2t, CC, CC, x, g_x2c);

    // --- block 2: ada_rmsnorm(x2) factors ---
    reduce_kernel<<<CC, 256>>>(g_x2c, g_sum, g_sumsq);
    gamma_kernel<<<1, 1024>>>(g_sum, g_sumsq, scale2, n2_w1, n2_b1, n2_w2, n2_b2, g_fac);

    // --- MLP (norm fused into A-stage of first GEMM) ---
    gemm_kernel<2, 1><<<dim3(MLPH/64, PP/128), 256>>>(g_x2c, g_fac, mlp_w1, mlp_b1, g_m1, MLPH, CC, nullptr, nullptr);
    gemm_kernel<3, 0><<<dim3(CC/64, PP/128), 256>>>(g_m1, nullptr, mlp_w2, mlp_b2, out, CC, MLPH, g_x2t, nullptr);
}